// round 3
// baseline (speedup 1.0000x reference)
#include <cuda_runtime.h>

#define BATCH   32
#define NNODES  2000
#define NEDGES  64000
#define EMBED   128
#define ACCW    8      // [sum_src_x, sum_src_y, sum_ea_x, sum_ea_y, count, pad, pad, pad]

// Scratch accumulator: [B][N][8] floats = 2 MB (device global, 32B-aligned rows).
__device__ __align__(16) float g_acc[BATCH * NNODES * ACCW];

__global__ __launch_bounds__(256) void zero_acc_kernel() {
    int i = blockIdx.x * blockDim.x + threadIdx.x;
    float4* p = (float4*)g_acc;
    if (i < BATCH * NNODES * ACCW / 4) p[i] = make_float4(0.f, 0.f, 0.f, 0.f);
}

__device__ __forceinline__ void red_v4(float* ptr, float x, float y, float z, float w) {
    asm volatile("red.global.add.v4.f32 [%0], {%1, %2, %3, %4};"
                 :: "l"(ptr), "f"(x), "f"(y), "f"(z), "f"(w) : "memory");
}
__device__ __forceinline__ void red_f32(float* ptr, float v) {
    asm volatile("red.global.add.f32 [%0], %1;" :: "l"(ptr), "f"(v) : "memory");
}

// 2 edges per thread; scatter via global reduction (distributed across all LTS).
__global__ __launch_bounds__(256) void accumulate_kernel(
    const float* __restrict__ locs,      // [B, N, 2]
    const int* __restrict__ edge_index,  // [B, 2, E] int32 (JAX x64 disabled)
    const float* __restrict__ edge_attr) // [B, E, 2]
{
    const int pair = blockIdx.x * blockDim.x + threadIdx.x;   // handles edges 2*pair, 2*pair+1
    const int total_pairs = BATCH * NEDGES / 2;
    if (pair >= total_pairs) return;

    const int pairs_per_batch = NEDGES / 2;
    const int b  = pair / pairs_per_batch;
    const int ep = pair - b * pairs_per_batch;
    const int e  = ep * 2;

    const int* src_p = edge_index + (long long)b * 2 * NEDGES;
    const int* tgt_p = src_p + NEDGES;
    const float2* loc2 = (const float2*)(locs + (long long)b * NNODES * 2);

    int2 s2 = *(const int2*)(src_p + e);
    int2 t2 = *(const int2*)(tgt_p + e);
    float4 ea = *(const float4*)(edge_attr + ((long long)b * NEDGES + e) * 2);

    float* accb = g_acc + (long long)b * NNODES * ACCW;

    if ((unsigned)s2.x < NNODES && (unsigned)t2.x < NNODES) {
        float2 xs = __ldg(&loc2[s2.x]);
        float* row = accb + t2.x * ACCW;
        red_v4(row, xs.x, xs.y, ea.x, ea.y);
        red_f32(row + 4, 1.0f);
    }
    if ((unsigned)s2.y < NNODES && (unsigned)t2.y < NNODES) {
        float2 xs = __ldg(&loc2[s2.y]);
        float* row = accb + t2.y * ACCW;
        red_v4(row, xs.x, xs.y, ea.z, ea.w);
        red_f32(row + 4, 1.0f);
    }
}

// 4 output elements per thread (float4 store). Node index is warp-uniform
// (threads 0..31 cover d=0..127 of one node) -> acc/locs loads broadcast.
__global__ __launch_bounds__(256) void compute_kernel(
    const float* __restrict__ locs,   // [B, N, 2]
    const float* __restrict__ W,      // [128, 6]
    const float* __restrict__ bias,   // [128]
    float* __restrict__ out)          // [B, N, 128]
{
    int tid = blockIdx.x * blockDim.x + threadIdx.x;
    const int total = BATCH * NNODES * EMBED / 4;
    if (tid >= total) return;

    int d4 = (tid & (EMBED / 4 - 1)) * 4;   // first of 4 embed dims
    int bn = tid >> 5;                      // b*N + n

    const float* acc = g_acc + (long long)bn * ACCW;
    float4 sums = *(const float4*)acc;      // broadcast within warp
    float  cnt  = acc[4];

    float4 o = make_float4(0.f, 0.f, 0.f, 0.f);
    if (cnt > 0.0f) {
        float inv = 1.0f / cnt;
        float f0 = __ldg(&locs[(long long)bn * 2 + 0]);
        float f1 = __ldg(&locs[(long long)bn * 2 + 1]);
        float f2 = sums.x * inv;
        float f3 = sums.y * inv;
        float f4 = sums.z * inv;
        float f5 = sums.w * inv;

        #pragma unroll
        for (int k = 0; k < 4; k++) {
            int d = d4 + k;
            const float* w = W + d * 6;
            float v = __ldg(&bias[d]);
            v = fmaf(__ldg(w + 0), f0, v);
            v = fmaf(__ldg(w + 1), f1, v);
            v = fmaf(__ldg(w + 2), f2, v);
            v = fmaf(__ldg(w + 3), f3, v);
            v = fmaf(__ldg(w + 4), f4, v);
            v = fmaf(__ldg(w + 5), f5, v);
            ((float*)&o)[k] = v;
        }
    }
    ((float4*)out)[tid] = o;
}

extern "C" void kernel_launch(void* const* d_in, const int* in_sizes, int n_in,
                              void* d_out, int out_size) {
    const float* locs       = (const float*)d_in[0];
    const int*   edge_index = (const int*)d_in[1];
    const float* edge_attr  = (const float*)d_in[2];
    const float* W          = (const float*)d_in[3];
    const float* bias       = (const float*)d_in[4];
    float*       out        = (float*)d_out;

    (void)in_sizes; (void)n_in; (void)out_size;

    // 1) zero scratch (float4 stores)
    zero_acc_kernel<<<(BATCH * NNODES * ACCW / 4 + 255) / 256, 256>>>();

    // 2) scatter 5-vector per (batch, target) via red.global (v4 + scalar)
    int pairs = BATCH * NEDGES / 2;
    accumulate_kernel<<<(pairs + 255) / 256, 256>>>(locs, edge_index, edge_attr);

    // 3) dense epilogue: out = W @ [x_t, mean_src, mean_ea] + b
    int total4 = BATCH * NNODES * EMBED / 4;
    compute_kernel<<<(total4 + 255) / 256, 256>>>(locs, W, bias, out);
}